// round 6
// baseline (speedup 1.0000x reference)
#include <cuda_runtime.h>

// Fixed shapes from reference setup_inputs
#define BB    32        // batch
#define TT    4000      // frames per batch
#define NB    65        // nbands
#define LF    129       // FIR length = 2*NB-1
#define FS    80        // framesize (hop)
#define FPB   25        // frames per block tile (kernel B)
#define EF    28        // staged frames (t0-2 .. t0+25)
#define TILES 160       // TT / FPB
#define OUTW  320000    // TT*FS
#define WROW  147       // padded firwin row stride
#define XROW  84        // x staging row stride (80 + pad, float4-aligned)
#define NTHR  256
#define NFRM  (BB*TT)   // 128000 flat frames
#define ZPST  68        // zp scratch row stride (float4-aligned)
#define ANF   64        // frames per block in kernel A

__device__ float g_zp[NFRM * ZPST];  // 34.8 MB scratch: zero-phase half-IR per frame

// ---------------- Kernel A: zp[n][d] = sum_k H[n][k] * T[d][k] ----------------
// T[d][k] = (k==0 ? 1 : 2*cos(2*pi*(k*d mod 129)/129)) / 129, built per-block via MUFU cospif.
// Block: 64 frames. Warp w owns frames f0=8w..8w+7; lane l owns d = l and l+33.
__global__ void __launch_bounds__(NTHR)
zp_kernel(const float* __restrict__ H) {
    __shared__ __align__(16) float sTa[NB * ZPST];   // 17680 B
    __shared__ __align__(16) float sHa[ANF * ZPST];  // 17408 B

    const int tid = threadIdx.x;
    const int n0  = blockIdx.x * ANF;

    for (int i = tid; i < NB * NB; i += NTHR) {
        int d = i / NB, k = i - (i / NB) * NB;
        int m = (k * d) % LF;
        float c = cospif(2.0f * (float)m * (1.0f / 129.0f));
        sTa[d * ZPST + k] = (k == 0) ? (1.0f / 129.0f) : (2.0f / 129.0f) * c;
    }
    for (int i = tid; i < ANF * NB; i += NTHR) {
        int f = i / NB, k = i - f * NB;
        sHa[f * ZPST + k] = H[(size_t)(n0 + f) * NB + k];
    }
    __syncthreads();

    const int w = tid >> 5, l = tid & 31;
    const int f0 = w * 8;
    const float* tr0 = &sTa[l * ZPST];
    const float* tr1 = &sTa[(l + 33) * ZPST];

    float acc0[8] = {0,0,0,0,0,0,0,0};
    float acc1[8] = {0,0,0,0,0,0,0,0};

    #pragma unroll 4
    for (int kc = 0; kc < 16; ++kc) {
        int k0 = kc * 4;
        float4 t0 = *reinterpret_cast<const float4*>(tr0 + k0);
        float4 t1 = *reinterpret_cast<const float4*>(tr1 + k0);
        #pragma unroll
        for (int j = 0; j < 8; ++j) {
            float4 hv = *reinterpret_cast<const float4*>(&sHa[(f0 + j) * ZPST + k0]);
            float a0 = acc0[j], a1 = acc1[j];
            a0 = fmaf(hv.x, t0.x, a0); a1 = fmaf(hv.x, t1.x, a1);
            a0 = fmaf(hv.y, t0.y, a0); a1 = fmaf(hv.y, t1.y, a1);
            a0 = fmaf(hv.z, t0.z, a0); a1 = fmaf(hv.z, t1.z, a1);
            a0 = fmaf(hv.w, t0.w, a0); a1 = fmaf(hv.w, t1.w, a1);
            acc0[j] = a0; acc1[j] = a1;
        }
    }
    {   // k = 64 tail
        float t0s = tr0[64], t1s = tr1[64];
        #pragma unroll
        for (int j = 0; j < 8; ++j) {
            float hs = sHa[(f0 + j) * ZPST + 64];
            acc0[j] = fmaf(hs, t0s, acc0[j]);
            acc1[j] = fmaf(hs, t1s, acc1[j]);
        }
    }
    #pragma unroll
    for (int j = 0; j < 8; ++j) {
        size_t row = (size_t)(n0 + f0 + j) * ZPST;
        g_zp[row + l]      = acc0[j];
        g_zp[row + l + 33] = acc1[j];
    }
    // d = 32 epilogue: threads 0..63, one frame each
    if (tid < ANF) {
        const float* tr = &sTa[32 * ZPST];
        const float* hr = &sHa[tid * ZPST];
        float s = 0.0f;
        #pragma unroll 5
        for (int k = 0; k < NB; ++k) s = fmaf(hr[k], tr[k], s);
        g_zp[(size_t)(n0 + tid) * ZPST + 32] = s;
    }
}

// ---------------- Kernel B: firwin expand + conv + overlap-add ----------------
__global__ void __launch_bounds__(NTHR)
fng_main(const float* __restrict__ noise, float* __restrict__ out) {
    __shared__ __align__(16) float sZ[EF * NB];       // 7280 B
    __shared__ __align__(16) float sW[EF * WROW];     // 16464 B (row: [0..7]=0, [8..136]=j0..128, [137..146]=0)
    __shared__ __align__(16) float sXr[EF * XROW];    // 9408 B  (x rows, stride 84)

    const int tid  = threadIdx.x;
    const int b    = blockIdx.x / TILES;
    const int tile = blockIdx.x - b * TILES;
    const int t0   = tile * FPB;

    // ---- stage zp rows (coalesced) and x = 2*noise-1 (zeros outside [0,TT)) ----
    for (int i = tid; i < EF * NB; i += NTHR) {
        int f = i / NB;
        int te = t0 - 2 + f;
        float v = 0.0f;
        if (te >= 0 && te < TT) v = g_zp[(size_t)(b * TT + te) * ZPST + (i - f * NB)];
        sZ[i] = v;
    }
    for (int i = tid; i < EF * FS; i += NTHR) {
        int f = i / FS;
        int te = t0 - 2 + f;
        float v = 0.0f;
        if (te >= 0 && te < TT) v = 2.0f * noise[((size_t)b * TT + te) * FS + (i - f * FS)] - 1.0f;
        sXr[f * XROW + (i - f * FS)] = v;
    }
    __syncthreads();

    // ---- expand padded firwin rows: sW[f][8+j] = zp[f][|j-64|]*hann[j] ----
    for (int i = tid; i < EF * WROW; i += NTHR) {
        int f = i / WROW;
        int j = (i - f * WROW) - 8;
        float v = 0.0f;
        if ((unsigned)j <= 128u) {
            int d = j - 64; d = (d < 0) ? -d : d;
            float hann = 0.5f - 0.5f * cospif(2.0f * (float)j * (1.0f / 129.0f));
            v = sZ[f * NB + d] * hann;
        }
        sW[i] = v;
    }
    __syncthreads();

    // ---- conv + OLA: thread owns 8 consecutive pre-trim outputs q = 80*t0 + 8g + r ----
    // 17 chunks of 8 samples; chunk weights = 15-wide band of one firwin row,
    // loaded as independent LDS (no serial slide chain); x via 2x LDS.128.
    const int groups = (tile == TILES - 1) ? 258 : 250;
    for (int g = tid; g < groups; g += NTHR) {
        if (tile == 0 && g < 8) continue;      // trimmed head
        const int ql0 = g * 8;
        const int sl0 = ql0 + 32;
        int f = sl0 / FS;
        int rem = sl0 - f * FS;
        int cb = (rem == 0) ? 10 : ((FS - rem) >> 3);   // chunk index of next frame boundary
        const float* wr = &sW[f * WROW];
        int xoff = sl0 + 4 * f;                          // sXr addr = slc + 4*frame
        float acc[8] = {0,0,0,0,0,0,0,0};

        #pragma unroll 1
        for (int c = 0; c < 17; ++c) {
            if (c == cb) { wr += WROW; cb += 10; xoff += 4; }
            float4 xa = *reinterpret_cast<const float4*>(&sXr[xoff]);
            float4 xb = *reinterpret_cast<const float4*>(&sXr[xoff + 4]);
            const float* bp = wr + (129 - 8 * c);        // band: j = 121-8c .. 135-8c (padded rows)
            float band[15];
            #pragma unroll
            for (int m = 0; m < 15; ++m) band[m] = bp[m];
            float xs[8] = {xa.x, xa.y, xa.z, xa.w, xb.x, xb.y, xb.z, xb.w};
            #pragma unroll
            for (int u = 0; u < 8; ++u) {
                float xv = xs[u];
                #pragma unroll
                for (int r = 0; r < 8; ++r)
                    acc[r] = fmaf(xv, band[7 + r - u], acc[r]);
            }
            xoff += 8;
        }

        int p = t0 * FS + ql0 - 64;            // trimmed position, multiple of 8
        float* op = &out[(size_t)b * OUTW + p];
        *reinterpret_cast<float4*>(op)     = make_float4(acc[0], acc[1], acc[2], acc[3]);
        *reinterpret_cast<float4*>(op + 4) = make_float4(acc[4], acc[5], acc[6], acc[7]);
    }
}

extern "C" void kernel_launch(void* const* d_in, const int* in_sizes, int n_in,
                              void* d_out, int out_size) {
    (void)in_sizes; (void)n_in; (void)out_size;
    const float* H     = (const float*)d_in[0];
    const float* noise = (const float*)d_in[1];
    float* out         = (float*)d_out;

    zp_kernel<<<NFRM / ANF, NTHR>>>(H);
    fng_main<<<BB * TILES, NTHR>>>(noise, out);
}

// round 7
// speedup vs baseline: 1.1940x; 1.1940x over previous
#include <cuda_runtime.h>

// Fixed shapes from reference setup_inputs
#define BB    32        // batch
#define TT    4000      // frames per batch
#define NB    65        // nbands
#define LF    129       // FIR length = 2*NB-1
#define FS    80        // framesize (hop)
#define FPB   25        // frames per block tile (kernel B)
#define EF    28        // staged frames (t0-2 .. t0+25)
#define TILES 160       // TT / FPB
#define OUTW  320000    // TT*FS
#define WROW  148       // padded firwin row stride: 11 zeros + 129 taps + 8 zeros
#define WPAD  11        // left zero pad (makes band base 132-8c float4-aligned)
#define NTHR  256
#define NFRM  (BB*TT)   // 128000 flat frames
#define ZPST  68        // zp scratch / smem row stride (float4-aligned)
#define ANF   64        // frames per chunk in kernel A
#define NCH   4         // chunks per block in kernel A
#define ZGRID 500       // NFRM / (ANF*NCH) * ... : 500 blocks x 4 chunks x 64 frames
#define XSZ   2520      // swizzled x staging size (2240 + 2240/32*4, rounded)

__device__ float g_zp[NFRM * ZPST];  // 34.8 MB scratch: zero-phase half-IR per frame

// ---------------- Kernel A: zp[n][d] = sum_k H[n][k] * T[d][k] ----------------
// T[d][k] = (k==0 ? 1 : 2*cos(2*pi*(k*d mod 129)/129)) / 129, built ONCE per block.
// Block processes NCH chunks of ANF frames; next chunk's H is prefetched into
// registers (H rows are contiguous -> pure linear LDG) during current compute.
__global__ void __launch_bounds__(NTHR)
zp_kernel(const float* __restrict__ H) {
    __shared__ __align__(16) float sTa[NB * ZPST];   // 17680 B
    __shared__ __align__(16) float sHa[ANF * ZPST];  // 17408 B

    const int tid = threadIdx.x;

    // ---- build cosine table (once per block) ----
    for (int i = tid; i < NB * NB; i += NTHR) {
        int d = i / NB, k = i - (i / NB) * NB;
        int m = (k * d) % LF;
        float c = cospif(2.0f * (float)m * (1.0f / 129.0f));
        sTa[d * ZPST + k] = (k == 0) ? (1.0f / 129.0f) : (2.0f / 129.0f) * c;
    }

    // ---- prefetch chunk 0 H into registers (linear, coalesced) ----
    float hreg[17];
    {
        size_t base = (size_t)(blockIdx.x * ANF) * NB;
        #pragma unroll
        for (int q = 0; q < 17; ++q) {
            int i = tid + NTHR * q;
            hreg[q] = (i < ANF * NB) ? H[base + i] : 0.0f;
        }
    }

    const int w = tid >> 5, l = tid & 31;
    const int f0 = w * 8;
    const float* tr0 = &sTa[l * ZPST];
    const float* tr1 = &sTa[(l + 33) * ZPST];

    for (int ch = 0; ch < NCH; ++ch) {
        const int n0 = blockIdx.x * ANF + ch * (ZGRID * ANF);

        __syncthreads();   // protect sHa overwrite (and sTa on first iter)
        #pragma unroll
        for (int q = 0; q < 17; ++q) {
            int i = tid + NTHR * q;
            if (i < ANF * NB) sHa[(i / NB) * ZPST + (i % NB)] = hreg[q];
        }
        __syncthreads();

        // prefetch next chunk while computing this one
        if (ch + 1 < NCH) {
            size_t base = (size_t)(blockIdx.x * ANF + (ch + 1) * (ZGRID * ANF)) * NB;
            #pragma unroll
            for (int q = 0; q < 17; ++q) {
                int i = tid + NTHR * q;
                hreg[q] = (i < ANF * NB) ? H[base + i] : 0.0f;
            }
        }

        float acc0[8] = {0,0,0,0,0,0,0,0};
        float acc1[8] = {0,0,0,0,0,0,0,0};

        #pragma unroll 4
        for (int kc = 0; kc < 16; ++kc) {
            int k0 = kc * 4;
            float4 t0 = *reinterpret_cast<const float4*>(tr0 + k0);
            float4 t1 = *reinterpret_cast<const float4*>(tr1 + k0);
            #pragma unroll
            for (int j = 0; j < 8; ++j) {
                float4 hv = *reinterpret_cast<const float4*>(&sHa[(f0 + j) * ZPST + k0]);
                float a0 = acc0[j], a1 = acc1[j];
                a0 = fmaf(hv.x, t0.x, a0); a1 = fmaf(hv.x, t1.x, a1);
                a0 = fmaf(hv.y, t0.y, a0); a1 = fmaf(hv.y, t1.y, a1);
                a0 = fmaf(hv.z, t0.z, a0); a1 = fmaf(hv.z, t1.z, a1);
                a0 = fmaf(hv.w, t0.w, a0); a1 = fmaf(hv.w, t1.w, a1);
                acc0[j] = a0; acc1[j] = a1;
            }
        }
        {   // k = 64 tail
            float t0s = tr0[64], t1s = tr1[64];
            #pragma unroll
            for (int j = 0; j < 8; ++j) {
                float hs = sHa[(f0 + j) * ZPST + 64];
                acc0[j] = fmaf(hs, t0s, acc0[j]);
                acc1[j] = fmaf(hs, t1s, acc1[j]);
            }
        }
        #pragma unroll
        for (int j = 0; j < 8; ++j) {
            size_t row = (size_t)(n0 + f0 + j) * ZPST;
            g_zp[row + l]      = acc0[j];
            g_zp[row + l + 33] = acc1[j];
        }
        // d = 32 epilogue: threads 0..63, one frame each
        if (tid < ANF) {
            const float* tr = &sTa[32 * ZPST];
            const float* hr = &sHa[tid * ZPST];
            float s = 0.0f;
            #pragma unroll 5
            for (int k = 0; k < NB; ++k) s = fmaf(hr[k], tr[k], s);
            g_zp[(size_t)(n0 + tid) * ZPST + 32] = s;
        }
    }
}

// ---------------- Kernel B: firwin expand + conv + overlap-add ----------------
__global__ void __launch_bounds__(NTHR)
fng_main(const float* __restrict__ noise, float* __restrict__ out) {
    __shared__ __align__(16) float sZ[EF * NB];    // 7280 B
    __shared__ __align__(16) float sW[EF * WROW];  // 16576 B ([0..10]=0, [11..139]=j0..128, [140..147]=0)
    __shared__ __align__(16) float sX[XSZ];        // 10080 B (linear + (s>>5)*4 swizzle)

    const int tid  = threadIdx.x;
    const int b    = blockIdx.x / TILES;
    const int tile = blockIdx.x - b * TILES;
    const int t0   = tile * FPB;

    // ---- stage zp rows (coalesced) and x = 2*noise-1 (zeros outside [0,TT)) ----
    for (int i = tid; i < EF * NB; i += NTHR) {
        int f = i / NB;
        int te = t0 - 2 + f;
        float v = 0.0f;
        if (te >= 0 && te < TT) v = g_zp[(size_t)(b * TT + te) * ZPST + (i - f * NB)];
        sZ[i] = v;
    }
    for (int i = tid; i < EF * FS; i += NTHR) {
        int f = i / FS;
        int te = t0 - 2 + f;
        float v = 0.0f;
        if (te >= 0 && te < TT) v = 2.0f * noise[((size_t)b * TT + te) * FS + (i - f * FS)] - 1.0f;
        sX[i + ((i >> 5) << 2)] = v;
    }
    __syncthreads();

    // ---- expand padded firwin rows: sW[f][WPAD+j] = zp[f][|j-64|]*hann[j] ----
    for (int i = tid; i < EF * WROW; i += NTHR) {
        int f = i / WROW;
        int j = (i - f * WROW) - WPAD;
        float v = 0.0f;
        if ((unsigned)j <= 128u) {
            int d = j - 64; d = (d < 0) ? -d : d;
            float hann = 0.5f - 0.5f * cospif(2.0f * (float)j * (1.0f / 129.0f));
            v = sZ[f * NB + d] * hann;
        }
        sW[i] = v;
    }
    __syncthreads();

    // ---- conv + OLA: thread owns 8 consecutive pre-trim outputs q = 80*t0 + 8g + r ----
    // 17 chunks of 8 samples; weights: 16-float band (4x LDS.128, bank-disjoint
    // across the <=4 active frame rows); x: 2x conflict-free LDS.128.
    const int groups = (tile == TILES - 1) ? 258 : 250;
    for (int g = tid; g < groups; g += NTHR) {
        if (tile == 0 && g < 8) continue;      // trimmed head
        const int ql0 = g * 8;
        const int sl0 = ql0 + 32;
        int f = sl0 / FS;
        int rem = sl0 - f * FS;
        int cb = (rem == 0) ? 10 : ((FS - rem) >> 3);   // chunk index of next frame boundary
        const float* wr = &sW[f * WROW];
        float acc[8] = {0,0,0,0,0,0,0,0};

        #pragma unroll 1
        for (int c = 0; c < 17; ++c) {
            if (c == cb) { wr += WROW; cb += 10; }
            int slc = sl0 + 8 * c;
            int xi = slc + ((slc >> 5) << 2);
            float4 xa = *reinterpret_cast<const float4*>(&sX[xi]);
            float4 xb = *reinterpret_cast<const float4*>(&sX[xi + 4]);
            const float* bp = wr + (132 - 8 * c);        // float4-aligned band base
            float4 b0 = *reinterpret_cast<const float4*>(bp);
            float4 b1 = *reinterpret_cast<const float4*>(bp + 4);
            float4 b2 = *reinterpret_cast<const float4*>(bp + 8);
            float4 b3 = *reinterpret_cast<const float4*>(bp + 12);
            float band[16] = {b0.x,b0.y,b0.z,b0.w, b1.x,b1.y,b1.z,b1.w,
                              b2.x,b2.y,b2.z,b2.w, b3.x,b3.y,b3.z,b3.w};
            float xs[8] = {xa.x, xa.y, xa.z, xa.w, xb.x, xb.y, xb.z, xb.w};
            #pragma unroll
            for (int u = 0; u < 8; ++u) {
                float xv = xs[u];
                #pragma unroll
                for (int r = 0; r < 8; ++r)
                    acc[r] = fmaf(xv, band[7 + r - u], acc[r]);
            }
        }

        int p = t0 * FS + ql0 - 64;            // trimmed position, multiple of 8
        float* op = &out[(size_t)b * OUTW + p];
        *reinterpret_cast<float4*>(op)     = make_float4(acc[0], acc[1], acc[2], acc[3]);
        *reinterpret_cast<float4*>(op + 4) = make_float4(acc[4], acc[5], acc[6], acc[7]);
    }
}

extern "C" void kernel_launch(void* const* d_in, const int* in_sizes, int n_in,
                              void* d_out, int out_size) {
    (void)in_sizes; (void)n_in; (void)out_size;
    const float* H     = (const float*)d_in[0];
    const float* noise = (const float*)d_in[1];
    float* out         = (float*)d_out;

    zp_kernel<<<ZGRID, NTHR>>>(H);
    fng_main<<<BB * TILES, NTHR>>>(noise, out);
}

// round 8
// speedup vs baseline: 1.4904x; 1.2482x over previous
#include <cuda_runtime.h>

// Fixed shapes from reference setup_inputs
#define BB    32        // batch
#define TT    4000      // frames per batch
#define NB    65        // nbands
#define LF    129       // FIR length = 2*NB-1
#define FS    80        // framesize (hop)
#define FPB   25        // frames per block tile (kernel B)
#define EF    28        // staged frames (t0-2 .. t0+25)
#define TILES 160       // TT / FPB
#define OUTW  320000    // TT*FS
#define WROW  148       // padded firwin row stride: 11 zeros + 129 taps + 8 zeros
#define WPAD  11        // left zero pad (makes band base 132-8c float4-aligned)
#define NTHR  256
#define NFRM  (BB*TT)   // 128000 flat frames
#define ZPST  68        // smem H/T row stride (float4-aligned)
#define ANF   64        // frames per chunk in kernel A
#define NCH   4         // chunks per block in kernel A
#define ZGRID 500       // 500 blocks x 4 chunks x 64 frames = 128000
#define XSZ   2520      // swizzled x staging size

// Pre-expanded firwin rows: [0..10]=0, [11..139]=taps j0..j128, [140..147]=0.
// Pads are NEVER written -> remain zero from BSS zero-init.
__device__ __align__(16) float g_w[NFRM * WROW];   // 75.8 MB

// ---------------- Kernel A: firwin rows directly ----------------
// zp[d] = sum_k H[k]*T[d][k];  w[j] = zp[|j-64|] * hann[j]  (j = 0..128)
// T built once per block via MUFU cospif. Block does NCH chunks of ANF frames,
// next chunk's H prefetched into registers (linear LDG) during compute.
// Warp w: frames f0=8w..8w+7; lane l: d = l and l+33 -> taps {64-l,64+l,31-l,97+l}.
__global__ void __launch_bounds__(NTHR)
zp_kernel(const float* __restrict__ H) {
    __shared__ __align__(16) float sTa[NB * ZPST];   // 17680 B
    __shared__ __align__(16) float sHa[ANF * ZPST];  // 17408 B
    __shared__ float sHann[LF + 3];                  // 528 B

    const int tid = threadIdx.x;

    // ---- build cosine table + hann (once per block) ----
    for (int i = tid; i < NB * NB; i += NTHR) {
        int d = i / NB, k = i - (i / NB) * NB;
        int m = (k * d) % LF;
        float c = cospif(2.0f * (float)m * (1.0f / 129.0f));
        sTa[d * ZPST + k] = (k == 0) ? (1.0f / 129.0f) : (2.0f / 129.0f) * c;
        if (i < LF)
            sHann[i] = 0.5f - 0.5f * cospif(2.0f * (float)i * (1.0f / 129.0f));
    }

    // ---- prefetch chunk 0 H into registers (linear, coalesced) ----
    float hreg[17];
    {
        size_t base = (size_t)(blockIdx.x * ANF) * NB;
        #pragma unroll
        for (int q = 0; q < 17; ++q) {
            int i = tid + NTHR * q;
            hreg[q] = (i < ANF * NB) ? H[base + i] : 0.0f;
        }
    }
    __syncthreads();   // sHann/sTa visible

    const int w = tid >> 5, l = tid & 31;
    const int f0 = w * 8;
    const float* tr0 = &sTa[l * ZPST];
    const float* tr1 = &sTa[(l + 33) * ZPST];
    const float h0a = sHann[64 - l];   // for zp[d=l]    -> j = 64-l
    const float h0b = sHann[64 + l];   //                -> j = 64+l
    const float h1a = sHann[31 - l];   // for zp[d=l+33] -> j = 31-l
    const float h1b = sHann[97 + l];   //                -> j = 97+l
    const float h32a = sHann[32], h32b = sHann[96];

    for (int ch = 0; ch < NCH; ++ch) {
        const int n0 = blockIdx.x * ANF + ch * (ZGRID * ANF);

        __syncthreads();   // protect sHa overwrite
        #pragma unroll
        for (int q = 0; q < 17; ++q) {
            int i = tid + NTHR * q;
            if (i < ANF * NB) sHa[(i / NB) * ZPST + (i % NB)] = hreg[q];
        }
        __syncthreads();

        // prefetch next chunk while computing this one
        if (ch + 1 < NCH) {
            size_t base = (size_t)(blockIdx.x * ANF + (ch + 1) * (ZGRID * ANF)) * NB;
            #pragma unroll
            for (int q = 0; q < 17; ++q) {
                int i = tid + NTHR * q;
                hreg[q] = (i < ANF * NB) ? H[base + i] : 0.0f;
            }
        }

        float acc0[8] = {0,0,0,0,0,0,0,0};
        float acc1[8] = {0,0,0,0,0,0,0,0};

        #pragma unroll 4
        for (int kc = 0; kc < 16; ++kc) {
            int k0 = kc * 4;
            float4 t0 = *reinterpret_cast<const float4*>(tr0 + k0);
            float4 t1 = *reinterpret_cast<const float4*>(tr1 + k0);
            #pragma unroll
            for (int j = 0; j < 8; ++j) {
                float4 hv = *reinterpret_cast<const float4*>(&sHa[(f0 + j) * ZPST + k0]);
                float a0 = acc0[j], a1 = acc1[j];
                a0 = fmaf(hv.x, t0.x, a0); a1 = fmaf(hv.x, t1.x, a1);
                a0 = fmaf(hv.y, t0.y, a0); a1 = fmaf(hv.y, t1.y, a1);
                a0 = fmaf(hv.z, t0.z, a0); a1 = fmaf(hv.z, t1.z, a1);
                a0 = fmaf(hv.w, t0.w, a0); a1 = fmaf(hv.w, t1.w, a1);
                acc0[j] = a0; acc1[j] = a1;
            }
        }
        {   // k = 64 tail
            float t0s = tr0[64], t1s = tr1[64];
            #pragma unroll
            for (int j = 0; j < 8; ++j) {
                float hs = sHa[(f0 + j) * ZPST + 64];
                acc0[j] = fmaf(hs, t0s, acc0[j]);
                acc1[j] = fmaf(hs, t1s, acc1[j]);
            }
        }

        // ---- expanded firwin stores (4 coalesced groups per frame row) ----
        #pragma unroll
        for (int j = 0; j < 8; ++j) {
            size_t row = (size_t)(n0 + f0 + j) * WROW + WPAD;
            g_w[row + 64 - l] = acc0[j] * h0a;
            g_w[row + 64 + l] = acc0[j] * h0b;
            g_w[row + 31 - l] = acc1[j] * h1a;
            g_w[row + 97 + l] = acc1[j] * h1b;
        }
        // d = 32 epilogue: threads 0..63, one frame each -> taps j = 32, 96
        if (tid < ANF) {
            const float* tr = &sTa[32 * ZPST];
            const float* hr = &sHa[tid * ZPST];
            float s = 0.0f;
            #pragma unroll 5
            for (int k = 0; k < NB; ++k) s = fmaf(hr[k], tr[k], s);
            size_t row = (size_t)(n0 + tid) * WROW + WPAD;
            g_w[row + 32] = s * h32a;
            g_w[row + 96] = s * h32b;
        }
    }
}

// ---------------- Kernel B: conv + overlap-add ----------------
__global__ void __launch_bounds__(NTHR)
fng_main(const float* __restrict__ noise, float* __restrict__ out) {
    __shared__ __align__(16) float sW[EF * WROW];  // 16576 B (pre-expanded rows)
    __shared__ __align__(16) float sX[XSZ];        // 10080 B (linear + (s>>5)*4 swizzle)

    const int tid  = threadIdx.x;
    const int b    = blockIdx.x / TILES;
    const int tile = blockIdx.x - b * TILES;
    const int t0   = tile * FPB;

    // ---- stage firwin rows: pure linear float4 copy ----
    {
        float4* dst = reinterpret_cast<float4*>(sW);
        const int n4 = EF * WROW / 4;                  // 1036
        if (tile == 0) {
            const float4* s0 = reinterpret_cast<const float4*>(&g_w[(size_t)b * TT * WROW]);
            const int pad4 = 2 * WROW / 4;             // 74
            for (int i = tid; i < n4; i += NTHR)
                dst[i] = (i < pad4) ? make_float4(0.f,0.f,0.f,0.f) : s0[i - pad4];
        } else if (tile == TILES - 1) {
            const float4* src = reinterpret_cast<const float4*>(
                &g_w[(size_t)(b * TT + t0 - 2) * WROW]);
            const int lim4 = 27 * WROW / 4;            // 999
            for (int i = tid; i < n4; i += NTHR)
                dst[i] = (i < lim4) ? src[i] : make_float4(0.f,0.f,0.f,0.f);
        } else {
            const float4* src = reinterpret_cast<const float4*>(
                &g_w[(size_t)(b * TT + t0 - 2) * WROW]);
            for (int i = tid; i < n4; i += NTHR)
                dst[i] = src[i];
        }
    }
    // ---- stage x = 2*noise-1: linear float4 load, swizzled float4 store ----
    {
        const int n4 = EF * FS / 4;                    // 560
        if (tile == 0) {
            const float4* s0 = reinterpret_cast<const float4*>(&noise[(size_t)b * TT * FS]);
            const int pad4 = 2 * FS / 4;               // 40
            for (int i = tid; i < n4; i += NTHR) {
                float4 v = (i < pad4) ? make_float4(0.5f,0.5f,0.5f,0.5f) : s0[i - pad4];
                int i0 = i * 4;
                float4 x = make_float4(2.f*v.x-1.f, 2.f*v.y-1.f, 2.f*v.z-1.f, 2.f*v.w-1.f);
                *reinterpret_cast<float4*>(&sX[i0 + ((i0 >> 5) << 2)]) = x;
            }
        } else if (tile == TILES - 1) {
            const float4* src = reinterpret_cast<const float4*>(
                &noise[(size_t)(b * TT + t0 - 2) * FS]);
            const int lim4 = 27 * FS / 4;              // 540
            for (int i = tid; i < n4; i += NTHR) {
                float4 v = (i < lim4) ? src[i] : make_float4(0.5f,0.5f,0.5f,0.5f);
                int i0 = i * 4;
                float4 x = make_float4(2.f*v.x-1.f, 2.f*v.y-1.f, 2.f*v.z-1.f, 2.f*v.w-1.f);
                *reinterpret_cast<float4*>(&sX[i0 + ((i0 >> 5) << 2)]) = x;
            }
        } else {
            const float4* src = reinterpret_cast<const float4*>(
                &noise[(size_t)(b * TT + t0 - 2) * FS]);
            for (int i = tid; i < n4; i += NTHR) {
                float4 v = src[i];
                int i0 = i * 4;
                float4 x = make_float4(2.f*v.x-1.f, 2.f*v.y-1.f, 2.f*v.z-1.f, 2.f*v.w-1.f);
                *reinterpret_cast<float4*>(&sX[i0 + ((i0 >> 5) << 2)]) = x;
            }
        }
    }
    __syncthreads();

    // ---- conv + OLA: thread owns 8 consecutive pre-trim outputs q = 80*t0 + 8g + r ----
    const int groups = (tile == TILES - 1) ? 258 : 250;
    for (int g = tid; g < groups; g += NTHR) {
        if (tile == 0 && g < 8) continue;      // trimmed head
        const int ql0 = g * 8;
        const int sl0 = ql0 + 32;
        int f = sl0 / FS;
        int rem = sl0 - f * FS;
        int cb = (rem == 0) ? 10 : ((FS - rem) >> 3);   // chunk index of next frame boundary
        const float* wr = &sW[f * WROW];
        float acc[8] = {0,0,0,0,0,0,0,0};

        #pragma unroll 1
        for (int c = 0; c < 17; ++c) {
            if (c == cb) { wr += WROW; cb += 10; }
            int slc = sl0 + 8 * c;
            int xi = slc + ((slc >> 5) << 2);
            float4 xa = *reinterpret_cast<const float4*>(&sX[xi]);
            float4 xb = *reinterpret_cast<const float4*>(&sX[xi + 4]);
            const float* bp = wr + (132 - 8 * c);        // float4-aligned band base
            float4 b0 = *reinterpret_cast<const float4*>(bp);
            float4 b1 = *reinterpret_cast<const float4*>(bp + 4);
            float4 b2 = *reinterpret_cast<const float4*>(bp + 8);
            float4 b3 = *reinterpret_cast<const float4*>(bp + 12);
            float band[16] = {b0.x,b0.y,b0.z,b0.w, b1.x,b1.y,b1.z,b1.w,
                              b2.x,b2.y,b2.z,b2.w, b3.x,b3.y,b3.z,b3.w};
            float xs[8] = {xa.x, xa.y, xa.z, xa.w, xb.x, xb.y, xb.z, xb.w};
            #pragma unroll
            for (int u = 0; u < 8; ++u) {
                float xv = xs[u];
                #pragma unroll
                for (int r = 0; r < 8; ++r)
                    acc[r] = fmaf(xv, band[7 + r - u], acc[r]);
            }
        }

        int p = t0 * FS + ql0 - 64;            // trimmed position, multiple of 8
        float* op = &out[(size_t)b * OUTW + p];
        *reinterpret_cast<float4*>(op)     = make_float4(acc[0], acc[1], acc[2], acc[3]);
        *reinterpret_cast<float4*>(op + 4) = make_float4(acc[4], acc[5], acc[6], acc[7]);
    }
}

extern "C" void kernel_launch(void* const* d_in, const int* in_sizes, int n_in,
                              void* d_out, int out_size) {
    (void)in_sizes; (void)n_in; (void)out_size;
    const float* H     = (const float*)d_in[0];
    const float* noise = (const float*)d_in[1];
    float* out         = (float*)d_out;

    zp_kernel<<<ZGRID, NTHR>>>(H);
    fng_main<<<BB * TILES, NTHR>>>(noise, out);
}